// round 1
// baseline (speedup 1.0000x reference)
#include <cuda_runtime.h>
#include <math.h>

#define BB   64
#define SS   512
#define HH   768
#define A1N  100
#define NPAD 112
#define C1N  300
#define MM   (BB * SS)

// ---------------- scratch (no allocs allowed) ----------------
__device__ float g_token_att[MM];
__device__ float g_masked[MM];
__device__ float g_pooled[BB * HH];
__device__ float g_inv_sum[BB];
__device__ float g_maxlab[BB];
__device__ float g_minones[BB];
__device__ float g_maxmask[BB];
__device__ float g_tokloss[BB];
__device__ float g_sent[BB];

__device__ __forceinline__ float sigmoidf_(float x) { return 1.0f / (1.0f + expf(-x)); }

// ---------------- kernel 1: token attention scores ----------------
// token_att = sigmoid( tanh(X @ w1 + b1) @ w2 + b2 )   for all 32768 tokens.
// Block: 64 tokens x 112 padded cols, 256 threads (16x16), thread tile 4x7.
__global__ __launch_bounds__(256, 4)
void k_token_att(const float* __restrict__ hidden, const float* __restrict__ w1,
                 const float* __restrict__ b1, const float* __restrict__ w2,
                 const float* __restrict__ b2) {
    __shared__ __align__(16) float Xs[64][16];
    __shared__ float Ws[16][NPAD];
    __shared__ float b1s[NPAD];
    __shared__ float w2s[NPAD];

    const int tid = threadIdx.x;
    const int tx = tid & 15;        // col group (7 cols each)
    const int ty = tid >> 4;        // token group (4 tokens each)
    const int m0 = blockIdx.x * 64;

    if (tid < NPAD) {
        b1s[tid] = (tid < A1N) ? b1[tid] : 0.0f;
        w2s[tid] = (tid < A1N) ? w2[tid] : 0.0f;
    }

    float acc[4][7];
#pragma unroll
    for (int i = 0; i < 4; i++)
#pragma unroll
        for (int j = 0; j < 7; j++) acc[i][j] = 0.0f;

    for (int k0 = 0; k0 < HH; k0 += 16) {
        // load X tile: 64 tokens x 16 k, one float4 per thread
        {
            const int t  = tid >> 2;
            const int kk = (tid & 3) << 2;
            const float4 v = *reinterpret_cast<const float4*>(
                &hidden[(size_t)(m0 + t) * HH + k0 + kk]);
            *reinterpret_cast<float4*>(&Xs[t][kk]) = v;
        }
        // load W tile: 16 x 112 (cols >= 100 zero-padded), 7 elems per thread
#pragma unroll
        for (int i = 0; i < 7; i++) {
            const int idx = tid + (i << 8);      // 0..1791
            const int kk  = idx / NPAD;
            const int c   = idx - kk * NPAD;
            Ws[kk][c] = (c < A1N) ? w1[(k0 + kk) * A1N + c] : 0.0f;
        }
        __syncthreads();

#pragma unroll
        for (int kk = 0; kk < 16; kk++) {
            float xv[4], wv[7];
#pragma unroll
            for (int i = 0; i < 4; i++) xv[i] = Xs[ty * 4 + i][kk];
#pragma unroll
            for (int j = 0; j < 7; j++) wv[j] = Ws[kk][tx * 7 + j];
#pragma unroll
            for (int i = 0; i < 4; i++)
#pragma unroll
                for (int j = 0; j < 7; j++)
                    acc[i][j] = fmaf(xv[i], wv[j], acc[i][j]);
        }
        __syncthreads();
    }

    // epilogue: tanh, dot with w2 (padded cols contribute 0), reduce over tx, sigmoid
    const float b2v = b2[0];
#pragma unroll
    for (int i = 0; i < 4; i++) {
        float part = 0.0f;
#pragma unroll
        for (int j = 0; j < 7; j++) {
            const int c = tx * 7 + j;
            part += tanhf(acc[i][j] + b1s[c]) * w2s[c];
        }
#pragma unroll
        for (int off = 8; off > 0; off >>= 1)
            part += __shfl_down_sync(0xffffffffu, part, off, 16);
        if (tx == 0)
            g_token_att[m0 + ty * 4 + i] = sigmoidf_(part + b2v);
    }
}

// ---------------- kernel 2: segment max + masking + per-batch stats ----------------
__global__ __launch_bounds__(SS)
void k_segment(const float* __restrict__ labels, const int* __restrict__ offmap,
               float* __restrict__ out_masked /* may be null */) {
    const int b = blockIdx.x;
    const int s = threadIdx.x;
    const int gi = b * SS + s;

    __shared__ float segmax[SS];
    __shared__ int   wexcl[17];
    __shared__ float red[16][5];

    const float att  = g_token_att[gi];
    const int   off0 = offmap[2 * gi];
    const float lab  = labels[gi];
    const bool  ns   = (off0 == 0);

    const int lane = s & 31, warp = s >> 5;
    const unsigned bal = __ballot_sync(0xffffffffu, ns);
    const int incl = __popc(bal & (0xffffffffu >> (31 - lane))); // inclusive within warp
    if (lane == 31) wexcl[warp + 1] = incl;                      // warp total
    segmax[s] = 0.0f;
    __syncthreads();

    if (s == 0) {                 // tiny serial scan over 16 warp totals
        int run = 0;
        wexcl[0] = 0;
        for (int w = 1; w <= 16; w++) { run += wexcl[w]; wexcl[w] = run; }
    }
    __syncthreads();

    const int csum = incl + wexcl[warp];       // inclusive cumsum of word-starts
    const int seg  = max(csum - 1, 0);

    // segment max via int-bits atomicMax (token_att > 0 always)
    atomicMax(reinterpret_cast<int*>(&segmax[seg]), __float_as_int(att));
    __syncthreads();

    const float word_att = ns ? segmax[seg] : 0.0f;
    const bool  msk      = (lab != -1.0f) && ns;
    const float masked   = msk ? word_att : 0.0f;

    g_masked[gi] = masked;
    if (out_masked) out_masked[gi] = masked;

    const float zl   = (lab != -1.0f) ? lab : 0.0f;
    const float d    = masked - zl;
    float sumv = masked;
    float sq   = d * d;
    float mx   = masked;
    float ones = (masked == 0.0f) ? 1.0f : masked;
    float ml   = lab;

#pragma unroll
    for (int off = 16; off > 0; off >>= 1) {
        sumv += __shfl_down_sync(0xffffffffu, sumv, off);
        sq   += __shfl_down_sync(0xffffffffu, sq,   off);
        mx    = fmaxf(mx,   __shfl_down_sync(0xffffffffu, mx,   off));
        ones  = fminf(ones, __shfl_down_sync(0xffffffffu, ones, off));
        ml    = fmaxf(ml,   __shfl_down_sync(0xffffffffu, ml,   off));
    }
    if (lane == 0) {
        red[warp][0] = sumv; red[warp][1] = sq; red[warp][2] = mx;
        red[warp][3] = ones; red[warp][4] = ml;
    }
    __syncthreads();
    if (s == 0) {
        float a = 0.0f, bq = 0.0f, c = -1e30f, dn = 1e30f, e = -1e30f;
        for (int w = 0; w < 16; w++) {
            a += red[w][0]; bq += red[w][1];
            c = fmaxf(c, red[w][2]); dn = fminf(dn, red[w][3]); e = fmaxf(e, red[w][4]);
        }
        g_inv_sum[b] = 1.0f / a;
        g_tokloss[b] = bq;
        g_maxmask[b] = c;
        g_minones[b] = dn;
        g_maxlab[b]  = e;
    }
}

// ---------------- kernel 3: attention pooling einsum ----------------
__global__ __launch_bounds__(128)
void k_pool(const float* __restrict__ hidden) {
    const int b = blockIdx.y;
    const int h = blockIdx.x * 128 + threadIdx.x;
    __shared__ float wn[SS];
    const float inv = g_inv_sum[b];
    for (int i = threadIdx.x; i < SS; i += 128)
        wn[i] = g_masked[b * SS + i] * inv;
    __syncthreads();

    const float* hp = hidden + (size_t)b * SS * HH + h;
    float acc = 0.0f;
#pragma unroll 8
    for (int s = 0; s < SS; s++)
        acc = fmaf(hp[(size_t)s * HH], wn[s], acc);
    g_pooled[b * HH + h] = acc;
}

// ---------------- kernel 4: sentence classifier head ----------------
__global__ __launch_bounds__(320)
void k_sent(const float* __restrict__ sw1, const float* __restrict__ sb1,
            const float* __restrict__ sw2, const float* __restrict__ sb2) {
    const int b = blockIdx.x;
    const int c = threadIdx.x;
    __shared__ float ps[HH];
    __shared__ float red[10];
    for (int i = c; i < HH; i += 320) ps[i] = g_pooled[b * HH + i];
    __syncthreads();

    float val = 0.0f;
    if (c < C1N) {
        float acc = 0.0f;
#pragma unroll 4
        for (int k = 0; k < HH; k++)
            acc = fmaf(ps[k], sw1[k * C1N + c], acc);
        val = tanhf(acc + sb1[c]) * sw2[c];
    }
    const int lane = c & 31, warp = c >> 5;
#pragma unroll
    for (int off = 16; off > 0; off >>= 1)
        val += __shfl_down_sync(0xffffffffu, val, off);
    if (lane == 0) red[warp] = val;
    __syncthreads();
    if (c == 0) {
        float t = 0.0f;
        for (int w = 0; w < 10; w++) t += red[w];
        g_sent[b] = sigmoidf_(t + sb2[0]);
    }
}

// ---------------- kernel 5: losses + final output ----------------
__global__ __launch_bounds__(64)
void k_final(float* __restrict__ out, int out_size) {
    const int b = threadIdx.x;   // 64 threads
    __shared__ float sm[64][4];
    const float sl   = g_sent[b];
    const float slab = g_maxlab[b];
    const float d1 = sl - slab;
    sm[b][0] = d1 * d1;                         // sentence loss term
    sm[b][1] = g_tokloss[b];                    // token loss partial
    const float mo = g_minones[b];
    sm[b][2] = mo * mo;                         // reg_a term
    const float d2 = g_maxmask[b] - slab;
    sm[b][3] = d2 * d2;                         // reg_b term
    const int sent_off = 5 + MM + b;
    if (sent_off < out_size) out[sent_off] = sl;
    __syncthreads();
    if (b == 0) {
        float sloss = 0.0f, tloss = 0.0f, ra = 0.0f, rb = 0.0f;
        for (int i = 0; i < 64; i++) {
            sloss += sm[i][0]; tloss += sm[i][1]; ra += sm[i][2]; rb += sm[i][3];
        }
        const float total = sloss + tloss + 0.01f * (ra + rb);
        if (out_size > 0) out[0] = total;
        if (out_size > 1) out[1] = sloss;
        if (out_size > 2) out[2] = tloss;
        if (out_size > 3) out[3] = ra;
        if (out_size > 4) out[4] = rb;
    }
}

// ---------------- launch ----------------
extern "C" void kernel_launch(void* const* d_in, const int* in_sizes, int n_in,
                              void* d_out, int out_size) {
    const float* hidden = (const float*)d_in[0];
    const float* w1     = (const float*)d_in[1];
    const float* b1     = (const float*)d_in[2];
    const float* w2     = (const float*)d_in[3];
    const float* b2     = (const float*)d_in[4];
    const float* sw1    = (const float*)d_in[5];
    const float* sb1    = (const float*)d_in[6];
    const float* sw2    = (const float*)d_in[7];
    const float* sb2    = (const float*)d_in[8];
    const float* labels = (const float*)d_in[9];
    const int*   offmap = (const int*)d_in[10];
    float* out = (float*)d_out;

    // Expected layout: [total, sent_loss, tok_loss, reg_a, reg_b, masked(32768), sent(64)]
    float* out_masked = (out_size >= 5 + MM + BB) ? (out + 5) : nullptr;

    k_token_att<<<MM / 64, 256>>>(hidden, w1, b1, w2, b2);
    k_segment<<<BB, SS>>>(labels, offmap, out_masked);
    dim3 g3(HH / 128, BB);
    k_pool<<<g3, 128>>>(hidden);
    k_sent<<<BB, 320>>>(sw1, sb1, sw2, sb2);
    k_final<<<1, 64>>>(out, out_size);
}

// round 2
// speedup vs baseline: 2.7066x; 2.7066x over previous
#include <cuda_runtime.h>
#include <math.h>

#define BB   64
#define SS   512
#define HH   768
#define A1N  100
#define NPAD 112
#define NT   14          // 112 / 8 n-tiles
#define C1N  300
#define MM   (BB * SS)
#define KSP  6           // split-K factor for sentence head (768/6 = 128)
#define WSTRIDE 120      // smem stride for W tile (conflict-free B-frag LDS)

// ---------------- scratch (no allocs allowed) ----------------
__device__ float g_token_att[MM];
__device__ float g_masked[MM];
__device__ int   g_list[MM];
__device__ float g_wts[MM];
__device__ int   g_cnt[BB];
__device__ float g_pooled[BB * HH];
__device__ float g_spart[BB * KSP * 304];
__device__ float g_inv_sum[BB];
__device__ float g_maxlab[BB];
__device__ float g_minones[BB];
__device__ float g_maxmask[BB];
__device__ float g_tokloss[BB];
__device__ float g_sent[BB];

__device__ __forceinline__ float sigmoidf_(float x) { return 1.0f / (1.0f + expf(-x)); }

__device__ __forceinline__ unsigned f2tf32(float x) {
    unsigned r;
    asm("cvt.rna.tf32.f32 %0, %1;" : "=r"(r) : "f"(x));
    return r;
}

// ---------------- kernel 1: token attention scores (tf32 mma.sync) ----------------
// token_att = sigmoid( tanh(X @ w1 + b1) @ w2 + b2 ). Block = 128 tokens, 8 warps,
// each warp owns 16 tokens x 112 (padded) cols via m16n8k8 tf32 mma.
__global__ __launch_bounds__(256, 3)
void k_token_att(const float* __restrict__ hidden, const float* __restrict__ w1,
                 const float* __restrict__ b1, const float* __restrict__ w2,
                 const float* __restrict__ b2) {
    __shared__ float Ws[32 * WSTRIDE];   // 32 k x 112 n (tf32 bit patterns), stride 120
    __shared__ float b1s[NPAD];
    __shared__ float w2s[NPAD];

    const int tid  = threadIdx.x;
    const int lane = tid & 31;
    const int warp = tid >> 5;
    const int g    = lane >> 2;   // group id (row within 8)
    const int tg   = lane & 3;    // thread-in-group (k within 4)
    const int m0   = blockIdx.x * 128 + warp * 16;

    if (tid < NPAD) {
        b1s[tid] = (tid < A1N) ? b1[tid] : 0.0f;
        w2s[tid] = (tid < A1N) ? w2[tid] : 0.0f;
    }

    float acc[NT][4];
#pragma unroll
    for (int nt = 0; nt < NT; nt++)
#pragma unroll
        for (int j = 0; j < 4; j++) acc[nt][j] = 0.0f;

    const float* __restrict__ arow0 = hidden + (size_t)(m0 + g) * HH;
    const float* __restrict__ arow8 = hidden + (size_t)(m0 + g + 8) * HH;

    for (int k0 = 0; k0 < HH; k0 += 32) {
        // cooperative load of W tile: 32 k-rows x 112 cols (zero-pad >= 100)
#pragma unroll
        for (int i = 0; i < NT; i++) {
            const int idx = tid + (i << 8);       // 0 .. 3583
            const int kk  = idx / NPAD;
            const int c   = idx - kk * NPAD;
            const float v = (c < A1N) ? w1[(k0 + kk) * A1N + c] : 0.0f;
            Ws[kk * WSTRIDE + c] = __uint_as_float(f2tf32(v));
        }
        __syncthreads();

#pragma unroll
        for (int ks = 0; ks < 4; ks++) {
            const int kk = k0 + ks * 8;
            const unsigned a0 = f2tf32(arow0[kk + tg]);
            const unsigned a1 = f2tf32(arow8[kk + tg]);
            const unsigned a2 = f2tf32(arow0[kk + tg + 4]);
            const unsigned a3 = f2tf32(arow8[kk + tg + 4]);
#pragma unroll
            for (int nt = 0; nt < NT; nt++) {
                const unsigned bb0 = __float_as_uint(Ws[(ks * 8 + tg) * WSTRIDE + nt * 8 + g]);
                const unsigned bb1 = __float_as_uint(Ws[(ks * 8 + tg + 4) * WSTRIDE + nt * 8 + g]);
                asm volatile(
                    "mma.sync.aligned.m16n8k8.row.col.f32.tf32.tf32.f32 "
                    "{%0,%1,%2,%3}, {%4,%5,%6,%7}, {%8,%9}, {%0,%1,%2,%3};"
                    : "+f"(acc[nt][0]), "+f"(acc[nt][1]), "+f"(acc[nt][2]), "+f"(acc[nt][3])
                    : "r"(a0), "r"(a1), "r"(a2), "r"(a3), "r"(bb0), "r"(bb1));
            }
        }
        __syncthreads();
    }

    // epilogue: tanh, dot with w2, reduce over the 4-lane quad, sigmoid
    const float b2v = b2[0];
    float p0 = 0.0f, p1 = 0.0f;
#pragma unroll
    for (int nt = 0; nt < NT; nt++) {
#pragma unroll
        for (int j = 0; j < 2; j++) {
            const int c = nt * 8 + tg * 2 + j;
            p0 += tanhf(acc[nt][j]     + b1s[c]) * w2s[c];
            p1 += tanhf(acc[nt][2 + j] + b1s[c]) * w2s[c];
        }
    }
    p0 += __shfl_xor_sync(0xffffffffu, p0, 1);
    p0 += __shfl_xor_sync(0xffffffffu, p0, 2);
    p1 += __shfl_xor_sync(0xffffffffu, p1, 1);
    p1 += __shfl_xor_sync(0xffffffffu, p1, 2);
    if (tg == 0) {
        g_token_att[m0 + g]     = sigmoidf_(p0 + b2v);
        g_token_att[m0 + g + 8] = sigmoidf_(p1 + b2v);
    }
}

// ---------------- kernel 2: segment max + masking + stats + nonzero compaction ----------------
__global__ __launch_bounds__(SS)
void k_segment(const float* __restrict__ labels, const int* __restrict__ offmap,
               float* __restrict__ out_masked /* may be null */) {
    const int b = blockIdx.x;
    const int s = threadIdx.x;
    const int gi = b * SS + s;

    __shared__ float segmax[SS];
    __shared__ int   wexcl[17];
    __shared__ int   wexcl2[17];
    __shared__ float red[16][5];

    const float att  = g_token_att[gi];
    const int   off0 = offmap[2 * gi];
    const float lab  = labels[gi];
    const bool  ns   = (off0 == 0);

    const int lane = s & 31, warp = s >> 5;
    const unsigned lt = (1u << lane) - 1u;
    const unsigned bal = __ballot_sync(0xffffffffu, ns);
    const int incl = __popc(bal & (0xffffffffu >> (31 - lane)));
    if (lane == 31) wexcl[warp + 1] = incl;
    segmax[s] = 0.0f;
    __syncthreads();

    if (s == 0) {
        int run = 0; wexcl[0] = 0;
        for (int w = 1; w <= 16; w++) { run += wexcl[w]; wexcl[w] = run; }
    }
    __syncthreads();

    const int seg = max(incl + wexcl[warp] - 1, 0);
    atomicMax(reinterpret_cast<int*>(&segmax[seg]), __float_as_int(att));
    __syncthreads();

    const float word_att = ns ? segmax[seg] : 0.0f;
    const bool  msk      = (lab != -1.0f) && ns;
    const float masked   = msk ? word_att : 0.0f;

    g_masked[gi] = masked;
    if (out_masked) out_masked[gi] = masked;

    // deterministic compaction of nonzero masked entries
    const bool nz = (masked != 0.0f);
    const unsigned bal2 = __ballot_sync(0xffffffffu, nz);
    const int pos = __popc(bal2 & lt);
    if (lane == 31) wexcl2[warp + 1] = pos + (nz ? 1 : 0);
    __syncthreads();
    if (s == 0) {
        int run = 0; wexcl2[0] = 0;
        for (int w = 1; w <= 16; w++) { run += wexcl2[w]; wexcl2[w] = run; }
        g_cnt[b] = wexcl2[16];
    }
    __syncthreads();
    if (nz) {
        const int o = wexcl2[warp] + pos;
        g_list[b * SS + o] = s;
        g_wts[b * SS + o]  = masked;
    }

    const float zl = (lab != -1.0f) ? lab : 0.0f;
    const float d  = masked - zl;
    float sumv = masked;
    float sq   = d * d;
    float mx   = masked;
    float ones = nz ? masked : 1.0f;
    float ml   = lab;

#pragma unroll
    for (int off = 16; off > 0; off >>= 1) {
        sumv += __shfl_down_sync(0xffffffffu, sumv, off);
        sq   += __shfl_down_sync(0xffffffffu, sq,   off);
        mx    = fmaxf(mx,   __shfl_down_sync(0xffffffffu, mx,   off));
        ones  = fminf(ones, __shfl_down_sync(0xffffffffu, ones, off));
        ml    = fmaxf(ml,   __shfl_down_sync(0xffffffffu, ml,   off));
    }
    if (lane == 0) {
        red[warp][0] = sumv; red[warp][1] = sq; red[warp][2] = mx;
        red[warp][3] = ones; red[warp][4] = ml;
    }
    __syncthreads();
    if (s == 0) {
        float a = 0.0f, bq = 0.0f, c = -1e30f, dn = 1e30f, e = -1e30f;
        for (int w = 0; w < 16; w++) {
            a += red[w][0]; bq += red[w][1];
            c = fmaxf(c, red[w][2]); dn = fminf(dn, red[w][3]); e = fmaxf(e, red[w][4]);
        }
        g_inv_sum[b] = 1.0f / a;
        g_tokloss[b] = bq;
        g_maxmask[b] = c;
        g_minones[b] = dn;
        g_maxlab[b]  = e;
    }
}

// ---------------- kernel 3: sparse attention pooling ----------------
__global__ __launch_bounds__(128)
void k_pool(const float* __restrict__ hidden) {
    const int b = blockIdx.y;
    const int h = blockIdx.x * 128 + threadIdx.x;
    __shared__ int   ls[SS];
    __shared__ float ws[SS];
    const int   cnt = g_cnt[b];
    const float inv = g_inv_sum[b];
    for (int i = threadIdx.x; i < cnt; i += 128) {
        ls[i] = g_list[b * SS + i];
        ws[i] = g_wts[b * SS + i] * inv;
    }
    __syncthreads();

    const float* hp = hidden + (size_t)b * SS * HH + h;
    float a0 = 0.0f, a1 = 0.0f, a2 = 0.0f, a3 = 0.0f;
    int i = 0;
    for (; i + 4 <= cnt; i += 4) {
        a0 = fmaf(__ldg(&hp[(size_t)ls[i]     * HH]), ws[i],     a0);
        a1 = fmaf(__ldg(&hp[(size_t)ls[i + 1] * HH]), ws[i + 1], a1);
        a2 = fmaf(__ldg(&hp[(size_t)ls[i + 2] * HH]), ws[i + 2], a2);
        a3 = fmaf(__ldg(&hp[(size_t)ls[i + 3] * HH]), ws[i + 3], a3);
    }
    for (; i < cnt; i++)
        a0 = fmaf(__ldg(&hp[(size_t)ls[i] * HH]), ws[i], a0);
    g_pooled[b * HH + h] = (a0 + a1) + (a2 + a3);
}

// ---------------- kernel 4a: sentence hidden layer, split-K ----------------
__global__ __launch_bounds__(320)
void k_sent_a(const float* __restrict__ sw1) {
    const int b  = blockIdx.y;
    const int ks = blockIdx.x;
    const int k0 = ks * (HH / KSP);            // 128 k's per block
    const int c  = threadIdx.x;
    __shared__ float ps[HH / KSP];
    if (c < HH / KSP) ps[c] = g_pooled[b * HH + k0 + c];
    __syncthreads();

    if (c < C1N) {
        const float* wp = sw1 + (size_t)k0 * C1N + c;
        float a0 = 0.0f, a1 = 0.0f, a2 = 0.0f, a3 = 0.0f;
#pragma unroll 4
        for (int kk = 0; kk < HH / KSP; kk += 4) {
            a0 = fmaf(ps[kk],     __ldg(&wp[(size_t)(kk)     * C1N]), a0);
            a1 = fmaf(ps[kk + 1], __ldg(&wp[(size_t)(kk + 1) * C1N]), a1);
            a2 = fmaf(ps[kk + 2], __ldg(&wp[(size_t)(kk + 2) * C1N]), a2);
            a3 = fmaf(ps[kk + 3], __ldg(&wp[(size_t)(kk + 3) * C1N]), a3);
        }
        g_spart[(b * KSP + ks) * 304 + c] = (a0 + a1) + (a2 + a3);
    }
}

// ---------------- kernel 4b: finish sentence head ----------------
__global__ __launch_bounds__(320)
void k_sent_b(const float* __restrict__ sb1, const float* __restrict__ sw2,
              const float* __restrict__ sb2) {
    const int b = blockIdx.x;
    const int c = threadIdx.x;
    __shared__ float red[10];
    float val = 0.0f;
    if (c < C1N) {
        float s = 0.0f;
#pragma unroll
        for (int j = 0; j < KSP; j++) s += g_spart[(b * KSP + j) * 304 + c];
        val = tanhf(s + sb1[c]) * sw2[c];
    }
    const int lane = c & 31, warp = c >> 5;
#pragma unroll
    for (int off = 16; off > 0; off >>= 1)
        val += __shfl_down_sync(0xffffffffu, val, off);
    if (lane == 0) red[warp] = val;
    __syncthreads();
    if (c == 0) {
        float t = 0.0f;
        for (int w = 0; w < 10; w++) t += red[w];
        g_sent[b] = sigmoidf_(t + sb2[0]);
    }
}

// ---------------- kernel 5: losses + final output ----------------
__global__ __launch_bounds__(64)
void k_final(float* __restrict__ out, int out_size) {
    const int b = threadIdx.x;
    __shared__ float sm[64][4];
    const float sl   = g_sent[b];
    const float slab = g_maxlab[b];
    const float d1 = sl - slab;
    sm[b][0] = d1 * d1;
    sm[b][1] = g_tokloss[b];
    const float mo = g_minones[b];
    sm[b][2] = mo * mo;
    const float d2 = g_maxmask[b] - slab;
    sm[b][3] = d2 * d2;
    const int sent_off = 5 + MM + b;
    if (sent_off < out_size) out[sent_off] = sl;
    __syncthreads();
    if (b == 0) {
        float sloss = 0.0f, tloss = 0.0f, ra = 0.0f, rb = 0.0f;
        for (int i = 0; i < 64; i++) {
            sloss += sm[i][0]; tloss += sm[i][1]; ra += sm[i][2]; rb += sm[i][3];
        }
        const float total = sloss + tloss + 0.01f * (ra + rb);
        if (out_size > 0) out[0] = total;
        if (out_size > 1) out[1] = sloss;
        if (out_size > 2) out[2] = tloss;
        if (out_size > 3) out[3] = ra;
        if (out_size > 4) out[4] = rb;
    }
}

// ---------------- launch ----------------
extern "C" void kernel_launch(void* const* d_in, const int* in_sizes, int n_in,
                              void* d_out, int out_size) {
    const float* hidden = (const float*)d_in[0];
    const float* w1     = (const float*)d_in[1];
    const float* b1     = (const float*)d_in[2];
    const float* w2     = (const float*)d_in[3];
    const float* b2     = (const float*)d_in[4];
    const float* sw1    = (const float*)d_in[5];
    const float* sb1    = (const float*)d_in[6];
    const float* sw2    = (const float*)d_in[7];
    const float* sb2    = (const float*)d_in[8];
    const float* labels = (const float*)d_in[9];
    const int*   offmap = (const int*)d_in[10];
    float* out = (float*)d_out;

    float* out_masked = (out_size >= 5 + MM + BB) ? (out + 5) : nullptr;

    k_token_att<<<MM / 128, 256>>>(hidden, w1, b1, w2, b2);
    k_segment<<<BB, SS>>>(labels, offmap, out_masked);
    dim3 g3(HH / 128, BB);
    k_pool<<<g3, 128>>>(hidden);
    dim3 g4(KSP, BB);
    k_sent_a<<<g4, 320>>>(sw1);
    k_sent_b<<<BB, 320>>>(sb1, sw2, sb2);
    k_final<<<1, 64>>>(out, out_size);
}